// round 5
// baseline (speedup 1.0000x reference)
#include <cuda_runtime.h>
#include <cuda_bf16.h>

// Problem constants (from reference_code)
#define BATCH    16384
#define N_SPARSE 26
#define N_DENSE  13
#define VOCAB    100000
#define EMB      64

// One warp per batch row. Lane l covers embedding elements {2l, 2l+1} (float2).
__global__ __launch_bounds__(256, 8)
void fm_mtl_kernel(const int*   __restrict__ sparse,   // [B, 26]
                   const float* __restrict__ dense,    // [B, 13]
                   const float* __restrict__ emb1,     // [26, V, 1]
                   const float* __restrict__ emb2,     // [26, V, 64]
                   const float* __restrict__ W_dense,  // [13, 1]
                   const float* __restrict__ b_dense,  // [1]
                   const float* __restrict__ W_finish, // [1,1]
                   const float* __restrict__ b_finish, // [1]
                   const float* __restrict__ W_like,   // [1,1]
                   const float* __restrict__ b_like,   // [1]
                   float*       __restrict__ out)      // [2*B]: finish | like
{
    const int warp = (blockIdx.x * blockDim.x + threadIdx.x) >> 5;
    const int lane = threadIdx.x & 31;
    if (warp >= BATCH) return;
    const int row = warp;

    // ---- load this row's 26 indices into lanes 0..25 ----
    int myidx = 0;
    if (lane < N_SPARSE) myidx = __ldg(&sparse[row * N_SPARSE + lane]);

    // ---- first-order partials (ride along on low lanes) ----
    float fo = 0.f;
    if (lane < N_SPARSE)
        fo = __ldg(&emb1[(long)lane * VOCAB + myidx]);          // scalar embedding
    if (lane < N_DENSE)
        fo += __ldg(&dense[row * N_DENSE + lane]) * __ldg(&W_dense[lane]);

    // ---- second order: FM sum-square trick ----
    float s0 = 0.f, s1 = 0.f, q0 = 0.f, q1 = 0.f;
    #pragma unroll
    for (int f = 0; f < N_SPARSE; f++) {
        const int idx = __shfl_sync(0xffffffffu, myidx, f);
        const float2* p =
            reinterpret_cast<const float2*>(emb2 + ((long)f * VOCAB + idx) * EMB) + lane;
        const float2 v = __ldg(p);
        s0 += v.x;  s1 += v.y;
        q0 += v.x * v.x;  q1 += v.y * v.y;
    }
    // per-lane contribution to sum_e(summed^2 - squared)
    const float part = (s0 * s0 - q0) + (s1 * s1 - q1);

    // ---- combined warp reduction of first-order + 0.5 * second-order ----
    float r = fo + 0.5f * part;
    #pragma unroll
    for (int o = 16; o; o >>= 1)
        r += __shfl_xor_sync(0xffffffffu, r, o);

    if (lane == 0) {
        const float logit = r + __ldg(b_dense);
        const float zf = logit * __ldg(W_finish) + __ldg(b_finish);
        const float zl = logit * __ldg(W_like)   + __ldg(b_like);
        out[row]         = 1.f / (1.f + __expf(-zf));
        out[BATCH + row] = 1.f / (1.f + __expf(-zl));
    }
}

extern "C" void kernel_launch(void* const* d_in, const int* in_sizes, int n_in,
                              void* d_out, int out_size)
{
    const int*   sparse   = (const int*)  d_in[0];
    const float* dense    = (const float*)d_in[1];
    const float* emb1     = (const float*)d_in[2];
    const float* emb2     = (const float*)d_in[3];
    const float* W_dense  = (const float*)d_in[4];
    const float* b_dense  = (const float*)d_in[5];
    const float* W_finish = (const float*)d_in[6];
    const float* b_finish = (const float*)d_in[7];
    const float* W_like   = (const float*)d_in[8];
    const float* b_like   = (const float*)d_in[9];
    float* out = (float*)d_out;

    // 8 warps (rows) per 256-thread block
    const int rows_per_block = 256 / 32;
    const int grid = (BATCH + rows_per_block - 1) / rows_per_block;  // 2048
    fm_mtl_kernel<<<grid, 256>>>(sparse, dense, emb1, emb2,
                                 W_dense, b_dense, W_finish, b_finish,
                                 W_like, b_like, out);
}

// round 9
// speedup vs baseline: 1.0137x; 1.0137x over previous
#include <cuda_runtime.h>
#include <cuda_bf16.h>

// Problem constants (from reference_code)
#define BATCH    16384
#define N_SPARSE 26
#define N_DENSE  13
#define VOCAB    100000
#define EMB      64

// One warp per batch row. Lane l covers embedding elements {2l, 2l+1} (float2).
// All 26 field gathers are issued before any use (register-array buffering) so
// the full DRAM latency is covered by memory-level parallelism.
__global__ __launch_bounds__(256, 2)
void fm_mtl_kernel(const int*   __restrict__ sparse,   // [B, 26]
                   const float* __restrict__ dense,    // [B, 13]
                   const float* __restrict__ emb1,     // [26, V, 1]
                   const float* __restrict__ emb2,     // [26, V, 64]
                   const float* __restrict__ W_dense,  // [13, 1]
                   const float* __restrict__ b_dense,  // [1]
                   const float* __restrict__ W_finish, // [1,1]
                   const float* __restrict__ b_finish, // [1]
                   const float* __restrict__ W_like,   // [1,1]
                   const float* __restrict__ b_like,   // [1]
                   float*       __restrict__ out)      // [2*B]: finish | like
{
    const int warp = (blockIdx.x * blockDim.x + threadIdx.x) >> 5;
    const int lane = threadIdx.x & 31;
    if (warp >= BATCH) return;
    const int row = warp;

    // ---- load this row's 26 indices into lanes 0..25 ----
    int myidx = 0;
    if (lane < N_SPARSE) myidx = __ldg(&sparse[row * N_SPARSE + lane]);

    // ---- first-order partials (ride along on low lanes) ----
    float fo = 0.f;
    if (lane < N_SPARSE)
        fo = __ldg(&emb1[(unsigned)lane * VOCAB + (unsigned)myidx]);  // scalar embedding
    if (lane < N_DENSE)
        fo += __ldg(&dense[row * N_DENSE + lane]) * __ldg(&W_dense[lane]);

    // ---- second order: issue ALL 26 gathers first (max MLP), then reduce ----
    const float2* emb2v = reinterpret_cast<const float2*>(emb2);
    float2 v[N_SPARSE];
    #pragma unroll
    for (int f = 0; f < N_SPARSE; f++) {
        const int idx = __shfl_sync(0xffffffffu, myidx, f);
        // float2-unit offset: (f*VOCAB + idx)*32 + lane  (max ~83M, fits in u32)
        const unsigned off = ((unsigned)(f * VOCAB) + (unsigned)idx) * (EMB / 2) + lane;
        v[f] = __ldg(emb2v + off);
    }

    float s0 = 0.f, s1 = 0.f, q0 = 0.f, q1 = 0.f;
    #pragma unroll
    for (int f = 0; f < N_SPARSE; f++) {
        s0 += v[f].x;  q0 += v[f].x * v[f].x;
        s1 += v[f].y;  q1 += v[f].y * v[f].y;
    }
    // per-lane contribution to sum_e(summed^2 - squared)
    const float part = (s0 * s0 - q0) + (s1 * s1 - q1);

    // ---- combined warp reduction of first-order + 0.5 * second-order ----
    float r = fo + 0.5f * part;
    #pragma unroll
    for (int o = 16; o; o >>= 1)
        r += __shfl_xor_sync(0xffffffffu, r, o);

    if (lane == 0) {
        const float logit = r + __ldg(b_dense);
        const float zf = logit * __ldg(W_finish) + __ldg(b_finish);
        const float zl = logit * __ldg(W_like)   + __ldg(b_like);
        out[row]         = 1.f / (1.f + __expf(-zf));
        out[BATCH + row] = 1.f / (1.f + __expf(-zl));
    }
}

extern "C" void kernel_launch(void* const* d_in, const int* in_sizes, int n_in,
                              void* d_out, int out_size)
{
    const int*   sparse   = (const int*)  d_in[0];
    const float* dense    = (const float*)d_in[1];
    const float* emb1     = (const float*)d_in[2];
    const float* emb2     = (const float*)d_in[3];
    const float* W_dense  = (const float*)d_in[4];
    const float* b_dense  = (const float*)d_in[5];
    const float* W_finish = (const float*)d_in[6];
    const float* b_finish = (const float*)d_in[7];
    const float* W_like   = (const float*)d_in[8];
    const float* b_like   = (const float*)d_in[9];
    float* out = (float*)d_out;

    // 8 warps (rows) per 256-thread block
    const int rows_per_block = 256 / 32;
    const int grid = (BATCH + rows_per_block - 1) / rows_per_block;  // 2048
    fm_mtl_kernel<<<grid, 256>>>(sparse, dense, emb1, emb2,
                                 W_dense, b_dense, W_finish, b_finish,
                                 W_like, b_like, out);
}